// round 17
// baseline (speedup 1.0000x reference)
#include <cuda_runtime.h>
#include <cuda_bf16.h>
#include <math_constants.h>

// Problem constants
#define NB 8          // batch
#define NY 180        // RENDER
#define NX 91         // XDIM+1
#define NV 192        // TEMPLATERES
#define SCALE_IN  (32400.0f / 7077888.0f)  // RENDER^2 / TEMPLATERES^3
#define SCALE_OUT (2.0f / 32400.0f)        // 2 (r_k_val) / 180^2 (irfft2 norm)

#define NRB 180       // kB blocks per batch (1 row each)

typedef unsigned long long ull;

// Scratch (device globals; no allocation allowed)
__device__ float2 g_tmid[NB * NY * NX];    // after column iDFT:  [b][ky][x]
__device__ ull    g_cand[NB * NRB * 4];    // per-row top-4 packed keys
__device__ int    g_cnt[NB];               // last-block counters (reset in kernel A)

// ---- packed key helpers: (orderable float bits << 32) | ~index -------------
__device__ __forceinline__ unsigned f2ord(float v) {
    unsigned u = __float_as_uint(v);
    return (u & 0x80000000u) ? ~u : (u | 0x80000000u);
}
__device__ __forceinline__ float ord2f(unsigned ou) {
    unsigned u = (ou & 0x80000000u) ? (ou ^ 0x80000000u) : ~ou;
    return __uint_as_float(u);
}
__device__ __forceinline__ ull kmax(ull a, ull b) { return a > b ? a : b; }
__device__ __forceinline__ ull kmin(ull a, ull b) { return a < b ? a : b; }

// Branch-free merge of two desc-sorted 4-lists -> top-4 (cold path only).
__device__ __forceinline__ void merge4(ull& a0, ull& a1, ull& a2, ull& a3,
                                       ull b0, ull b1, ull b2, ull b3) {
    ull m0 = kmax(a0, b0);
    ull m1 = kmax(kmax(a1, b1), kmin(a0, b0));
    ull m2 = kmax(kmax(a2, b2), kmax(kmin(a0, b1), kmin(a1, b0)));
    ull m3 = kmax(kmax(a3, b3),
                  kmax(kmin(a1, b1), kmax(kmin(a0, b2), kmin(a2, b0))));
    a0 = m0; a1 = m1; a2 = m2; a3 = m3;
}

// complex rotate: w <- w * s
__device__ __forceinline__ void crot(float2& w, float2 s) {
    float tx = w.x * s.x - w.y * s.y;
    float ty = w.x * s.y + w.y * s.x;
    w.x = tx; w.y = ty;
}
__device__ __forceinline__ float2 cmul(float2 a, float2 b) {
    return make_float2(a.x * b.x - a.y * b.y, a.x * b.y + a.y * b.x);
}

// start twiddle e^{i r theta} for r in 0..3 given w1=e^{i theta}, w2=e^{i 2theta}
__device__ __forceinline__ float2 wstart(int r, float2 w1, float2 w2) {
    if (r == 0) return make_float2(1.0f, 0.0f);
    if (r == 1) return w1;
    if (r == 2) return w2;
    return cmul(w1, w2);
}

// ---------------------------------------------------------------------------
// Kernel A: block = (b, one column x). Phase 1: 180 threads sample the
// column's grid points into smem. Phase 2: 4 lanes per output ky (46 groups):
// lane r covers y = r (mod 4), split into TWO independent rotator chains
// (offsets r, r+4; step e^{i8theta}) for 2x ILP and half the chain latency;
// butterfly shfl_xor(2),(1); lanes 0..3 write {ky, 180-ky, 90+ky, 90-ky}.
// ---------------------------------------------------------------------------
__global__ __launch_bounds__(192) void kA_sample_ifft_y(
    const float* __restrict__ src,
    const float* __restrict__ rot,
    const float* __restrict__ ref)
{
    __shared__ float2 cols[NY];

    int bx = blockIdx.x;          // 0 .. NB*NX-1
    int x  = bx % NX;
    int b  = bx / NX;
    int t  = threadIdx.x;         // 0..191

    if (bx == 0 && t < NB) g_cnt[t] = 0;   // reset counters for kernel B

    // ---- Phase 1: sampling (one point per thread) ----
    if (t < NY) {
        int y = t;
        int g = y + 90; if (g >= 180) g -= 180;         // fftshift pre-map
        float gx = (float)x        * (1.0f / 96.0f);
        float gy = (float)(g - 90) * (1.0f / 96.0f);

        const float* R = rot + b * 9;
        float p0 = gx * R[0] + gy * R[3];
        float p1 = gx * R[1] + gy * R[4];
        float p2 = gx * R[2] + gy * R[5];

        float fx = (p0 + 1.0f) * 0.5f * 191.0f;
        float fy = (p1 + 1.0f) * 0.5f * 191.0f;
        float fz = (p2 + 1.0f) * 0.5f * 191.0f;
        float fx0 = floorf(fx), fy0 = floorf(fy), fz0 = floorf(fz);
        float wx = fx - fx0, wy = fy - fy0, wz = fz - fz0;
        int ix = (int)fx0, iy = (int)fy0, iz = (int)fz0;

        int xc0 = min(max(ix, 0), NV - 1),     xc1 = min(max(ix + 1, 0), NV - 1);
        int yc0 = min(max(iy, 0), NV - 1),     yc1 = min(max(iy + 1, 0), NV - 1);
        int zc0 = min(max(iz, 0), NV - 1),     zc1 = min(max(iz + 1, 0), NV - 1);
        float wx0 = (1.0f - wx) * (((unsigned)ix       < NV) ? 1.0f : 0.0f);
        float wx1 =         wx  * (((unsigned)(ix + 1) < NV) ? 1.0f : 0.0f);
        float wy0 = (1.0f - wy) * (((unsigned)iy       < NV) ? 1.0f : 0.0f);
        float wy1 =         wy  * (((unsigned)(iy + 1) < NV) ? 1.0f : 0.0f);
        float wz0 = (1.0f - wz) * (((unsigned)iz       < NV) ? 1.0f : 0.0f);
        float wz1 =         wz  * (((unsigned)(iz + 1) < NV) ? 1.0f : 0.0f);

        const float* vr = src + (size_t)b * 2 * NV * NV * NV;
        const float* vi = vr + (size_t)NV * NV * NV;

        size_t r00 = ((size_t)zc0 * NV + yc0) * NV;
        size_t r01 = ((size_t)zc0 * NV + yc1) * NV;
        size_t r10 = ((size_t)zc1 * NV + yc0) * NV;
        size_t r11 = ((size_t)zc1 * NV + yc1) * NV;

        float w000 = wz0 * wy0 * wx0, w001 = wz0 * wy0 * wx1;
        float w010 = wz0 * wy1 * wx0, w011 = wz0 * wy1 * wx1;
        float w100 = wz1 * wy0 * wx0, w101 = wz1 * wy0 * wx1;
        float w110 = wz1 * wy1 * wx0, w111 = wz1 * wy1 * wx1;

        float a000 = __ldg(vr + r00 + xc0), a001 = __ldg(vr + r00 + xc1);
        float a010 = __ldg(vr + r01 + xc0), a011 = __ldg(vr + r01 + xc1);
        float a100 = __ldg(vr + r10 + xc0), a101 = __ldg(vr + r10 + xc1);
        float a110 = __ldg(vr + r11 + xc0), a111 = __ldg(vr + r11 + xc1);
        float b000 = __ldg(vi + r00 + xc0), b001 = __ldg(vi + r00 + xc1);
        float b010 = __ldg(vi + r01 + xc0), b011 = __ldg(vi + r01 + xc1);
        float b100 = __ldg(vi + r10 + xc0), b101 = __ldg(vi + r10 + xc1);
        float b110 = __ldg(vi + r11 + xc0), b111 = __ldg(vi + r11 + xc1);

        float re = w000 * a000 + w001 * a001 + w010 * a010 + w011 * a011
                 + w100 * a100 + w101 * a101 + w110 * a110 + w111 * a111;
        float im = w000 * b000 + w001 * b001 + w010 * b010 + w011 * b011
                 + w100 * b100 + w101 * b101 + w110 * b110 + w111 * b111;
        re *= SCALE_IN;
        im *= SCALE_IN;

        const float* rp = ref + ((size_t)(b * NY + t) * NX + x) * 2;
        float rr = rp[0], ri = rp[1];
        cols[t] = make_float2(re * rr + im * ri, im * rr - re * ri);
    }
    __syncthreads();

    // ---- Phase 2: iDFT along y, dual quarter-chains per lane ----
    int ky = t >> 2;
    int r  = t & 3;
    bool active = (ky < 46);

    float AX = 0, AY = 0, BX = 0, BY = 0;
    if (active) {
        float s1, c1;
        sincospif((float)ky * (1.0f / 90.0f), &s1, &c1);   // theta = 2*pi*ky/180
        float2 w1 = make_float2(c1, s1);
        float2 w2 = make_float2(c1 * c1 - s1 * s1, 2.0f * c1 * s1);
        float2 w4 = cmul(w2, w2);
        float2 w8 = cmul(w4, w4);
        float2 wa = wstart(r, w1, w2);     // chain a: y = r, r+8, ...
        float2 wb = cmul(wa, w4);          // chain b: y = r+4, r+12, ...

        float AXa = 0, AYa = 0, BXa = 0, BYa = 0;
        float AXb = 0, AYb = 0, BXb = 0, BYb = 0;
#pragma unroll 2
        for (int j = 0; j < 22; j++) {     // pairs (r+8j, r+8j+4)
            int y = r + 8 * j;
            float2 va = cols[y];
            float2 vb = cols[y + 4];
            AXa += va.x * wa.x; AYa += va.y * wa.x;
            BXa += va.x * wa.y; BYa += va.y * wa.y;
            AXb += vb.x * wb.x; AYb += vb.y * wb.x;
            BXb += vb.x * wb.y; BYb += vb.y * wb.y;
            crot(wa, w8);
            crot(wb, w8);
        }
        {   // tail term: y = r + 176 (chain a, 23rd term)
            float2 va = cols[r + 176];
            AXa += va.x * wa.x; AYa += va.y * wa.x;
            BXa += va.x * wa.y; BYa += va.y * wa.y;
        }
        AX = AXa + AXb; AY = AYa + AYb;
        BX = BXa + BXb; BY = BYa + BYb;
    }
    AX += __shfl_xor_sync(0xFFFFFFFFu, AX, 2);
    AY += __shfl_xor_sync(0xFFFFFFFFu, AY, 2);
    BX += __shfl_xor_sync(0xFFFFFFFFu, BX, 2);
    BY += __shfl_xor_sync(0xFFFFFFFFu, BY, 2);
    float oAX = __shfl_xor_sync(0xFFFFFFFFu, AX, 1);
    float oAY = __shfl_xor_sync(0xFFFFFFFFu, AY, 1);
    float oBX = __shfl_xor_sync(0xFFFFFFFFu, BX, 1);
    float oBY = __shfl_xor_sync(0xFFFFFFFFu, BY, 1);

    if (active) {
        bool ev = ((r & 1) == 0);
        float AXe = ev ? AX : oAX, AXo = ev ? oAX : AX;
        float AYe = ev ? AY : oAY, AYo = ev ? oAY : AY;
        float BXe = ev ? BX : oBX, BXo = ev ? oBX : BX;
        float BYe = ev ? BY : oBY, BYo = ev ? oBY : BY;

        float2* base = g_tmid + (size_t)b * NY * NX + x;
        if (r == 0) {
            float SX = AXe + AXo, SY = AYe + AYo, TX = BXe + BXo, TY = BYe + BYo;
            base[(size_t)ky * NX] = make_float2(SX - TY, TX + SY);              // out[ky]
        } else if (r == 1) {
            float SX = AXe + AXo, SY = AYe + AYo, TX = BXe + BXo, TY = BYe + BYo;
            base[(size_t)((NY - ky) % NY) * NX] = make_float2(SX + TY, SY - TX); // out[180-ky]
        } else if (r == 2 && ky != 45) {
            float DX = AXe - AXo, DY = AYe - AYo, EX = BXe - BXo, EY = BYe - BYo;
            base[(size_t)(90 + ky) * NX] = make_float2(DX - EY, EX + DY);        // out[90+ky]
        } else if (r == 3 && ky != 45) {
            float DX = AXe - AXo, DY = AYe - AYo, EX = BXe - BXo, EY = BYe - BYo;
            base[(size_t)(90 - ky) * NX] = make_float2(DX + EY, DY - EX);        // out[90-ky]
        }
    }
}

// ---------------------------------------------------------------------------
// Kernel B: block = (b, one row ky). c2r inverse DFT along x (91 -> 180):
// 4 lanes per output m, lane r covers k = r (mod 4) split into TWO chains
// (step e^{i8theta}, ~11 iters each); butterfly shfl_xor(2,1); candidates
// for {m, 180-m, 90+m, 90-m} (duplicates dropped). Warp + block top-4 via
// REDUX. LAST block per batch merges 180*4 = 720 keys -> output.
// Output layout: [0,32) r_k_val (8,4); [32,96) trans (8,4,2).
// ---------------------------------------------------------------------------
__global__ __launch_bounds__(192) void kB_c2r_top4_final(float* __restrict__ out)
{
    __shared__ float2 rows[NX];
    __shared__ ull    wtop[6][4];
    __shared__ int    s_last;

    int bx = blockIdx.x;          // 0 .. NB*NRB-1
    int ky = bx % NRB;
    int b  = bx / NRB;
    int t  = threadIdx.x;         // 0..191

    if (t < NX) rows[t] = g_tmid[(size_t)(b * NY + ky) * NX + t];
    __syncthreads();

    int m = t >> 2;
    int r = t & 3;
    bool active = (m < 46);

    float A = 0, B = 0;           // A = sum ar*cos(k theta), B = sum ai*sin(k theta)
    if (active) {
        float s1, c1;
        sincospif((float)m * (1.0f / 90.0f), &s1, &c1);    // theta = 2*pi*m/180
        float2 w1 = make_float2(c1, s1);
        float2 w2 = make_float2(c1 * c1 - s1 * s1, 2.0f * c1 * s1);
        float2 w4 = cmul(w2, w2);
        float2 w8 = cmul(w4, w4);
        int k0 = (r == 0) ? 4 : r;                         // first k of this residue
        float2 wa = (r == 0) ? w4 : wstart(r, w1, w2);     // e^{i k0 theta}
        float2 wb = cmul(wa, w4);                          // chain b: k0+4

        float Aa = 0, Ba = 0, Ab = 0, Bb = 0;
        int k = k0;
#pragma unroll 2
        for (; k + 4 < 90; k += 8) {
            float2 ca = rows[k];
            float2 cb = rows[k + 4];
            Aa += ca.x * wa.x; Ba += ca.y * wa.y;
            Ab += cb.x * wb.x; Bb += cb.y * wb.y;
            crot(wa, w8);
            crot(wb, w8);
        }
        if (k < 90) {             // odd tail (r==1: k=89)
            float2 ca = rows[k];
            Aa += ca.x * wa.x; Ba += ca.y * wa.y;
        }
        A = Aa + Ab; B = Ba + Bb;
    }
    A += __shfl_xor_sync(0xFFFFFFFFu, A, 2);
    B += __shfl_xor_sync(0xFFFFFFFFu, B, 2);
    float oA = __shfl_xor_sync(0xFFFFFFFFu, A, 1);
    float oB = __shfl_xor_sync(0xFFFFFFFFu, B, 1);

    unsigned myv = 0, myi = 0xFFFFFFFFu;   // candidate (ord value, index)
    if (active) {
        bool ev = ((r & 1) == 0);
        float Ae = ev ? A : oA, Ao = ev ? oA : A;
        float Be = ev ? B : oB, Bo = ev ? oB : B;
        float base = rows[0].x + ((m & 1) ? -rows[90].x : rows[90].x);

        float val; unsigned gi; bool emit = true;
        unsigned gb = (unsigned)(ky * NY);
        if (r == 0) {
            val = base + 2.0f * ((Ae - Be) + (Ao - Bo));   // r[m]
            gi = gb + (unsigned)m;
        } else if (r == 1) {
            val = base + 2.0f * ((Ae + Be) + (Ao + Bo));   // r[180-m]
            gi = gb + (unsigned)((NY - m) % NY);
            emit = (m != 0);
        } else if (r == 2) {
            val = base + 2.0f * ((Ae - Be) - (Ao - Bo));   // r[90+m]
            gi = gb + (unsigned)(90 + m);
            emit = (m != 45);
        } else {
            val = base + 2.0f * ((Ae + Be) - (Ao + Bo));   // r[90-m]
            gi = gb + (unsigned)(90 - m);
            emit = (m != 0 && m != 45);
        }
        if (emit) { myv = f2ord(val * SCALE_OUT); myi = gi; }
    }

    // ---- warp top-4 via REDUX (4 pop iterations; all lanes participate) ----
    ull wk0, wk1, wk2, wk3;
    {
        unsigned v = myv, idx = myi;
#define TOP_ITER(DST)                                                       \
        {                                                                   \
            unsigned mv = __reduce_max_sync(0xFFFFFFFFu, v);                \
            unsigned ci = (v == mv) ? idx : 0xFFFFFFFFu;                    \
            unsigned mi = __reduce_min_sync(0xFFFFFFFFu, ci);               \
            if (v == mv && idx == mi) { v = 0; idx = 0xFFFFFFFFu; }         \
            DST = ((ull)mv << 32) | (unsigned)(~mi);                        \
        }
        TOP_ITER(wk0) TOP_ITER(wk1) TOP_ITER(wk2) TOP_ITER(wk3)
    }
    int wid = t >> 5, lane = t & 31;
    if (lane == 0) { wtop[wid][0] = wk0; wtop[wid][1] = wk1; wtop[wid][2] = wk2; wtop[wid][3] = wk3; }
    __syncthreads();

    // ---- block top-4: one warp reduces the 24 warp keys ----
    if (t < 32) {
        unsigned v = 0, idx = 0xFFFFFFFFu;
        if (t < 24) {
            ull kk = (&wtop[0][0])[t];
            v = (unsigned)(kk >> 32);
            idx = ~((unsigned)(kk & 0xFFFFFFFFu));
        }
        ull bk0, bk1, bk2, bk3;
        {
            unsigned vv = v, ii = idx;
#define TOPB_ITER(DST)                                                      \
            {                                                               \
                unsigned mv = __reduce_max_sync(0xFFFFFFFFu, vv);           \
                unsigned ci = (vv == mv) ? ii : 0xFFFFFFFFu;                \
                unsigned mi = __reduce_min_sync(0xFFFFFFFFu, ci);           \
                if (vv == mv && ii == mi) { vv = 0; ii = 0xFFFFFFFFu; }     \
                DST = ((ull)mv << 32) | (unsigned)(~mi);                    \
            }
            TOPB_ITER(bk0) TOPB_ITER(bk1) TOPB_ITER(bk2) TOPB_ITER(bk3)
        }
        if (t == 0) {
            ull* c = g_cand + (size_t)(b * NRB + ky) * 4;
            c[0] = bk0; c[1] = bk1; c[2] = bk2; c[3] = bk3;
            __threadfence();
            int prev = atomicAdd(&g_cnt[b], 1);
            s_last = (prev == NRB - 1);
        }
    }
    __syncthreads();

    // ---- last block of this batch: merge all 180*4 = 720 candidates ----
    if (s_last) {
        __threadfence();          // acquire: make all g_cand writes visible
        const ull* cand = g_cand + (size_t)b * NRB * 4;
        ull c0 = 0, c1 = 0, c2 = 0, c3 = 0;
#pragma unroll
        for (int j = 0; j < 4; j++) {
            int i = t + j * 192;
            ull xk = (i < NRB * 4) ? cand[i] : 0;
            merge4(c0, c1, c2, c3, xk, 0, 0, 0);
        }
#pragma unroll
        for (int s = 16; s > 0; s >>= 1) {
            ull b0 = __shfl_xor_sync(0xFFFFFFFFu, c0, s);
            ull b1 = __shfl_xor_sync(0xFFFFFFFFu, c1, s);
            ull b2 = __shfl_xor_sync(0xFFFFFFFFu, c2, s);
            ull b3 = __shfl_xor_sync(0xFFFFFFFFu, c3, s);
            merge4(c0, c1, c2, c3, b0, b1, b2, b3);
        }
        __syncthreads();          // wtop reuse safe
        if (lane == 0) { wtop[wid][0] = c0; wtop[wid][1] = c1; wtop[wid][2] = c2; wtop[wid][3] = c3; }
        __syncthreads();
        if (t == 0) {
            ull r0 = wtop[0][0], r1 = wtop[0][1], r2 = wtop[0][2], r3 = wtop[0][3];
#pragma unroll
            for (int w = 1; w < 6; w++)
                merge4(r0, r1, r2, r3, wtop[w][0], wtop[w][1], wtop[w][2], wtop[w][3]);
            ull rs[4] = { r0, r1, r2, r3 };
#pragma unroll
            for (int k = 0; k < 4; k++) {
                ull kk = rs[k];
                float v = ord2f((unsigned)(kk >> 32));
                unsigned gi = ~((unsigned)(kk & 0xFFFFFFFFu));
                int mm = (int)(gi % NY);
                int yy = (int)(gi / NY);
                out[b * 4 + k] = v;
                out[32 + (b * 4 + k) * 2 + 0] = (float)(mm - 90);
                out[32 + (b * 4 + k) * 2 + 1] = (float)(yy - 90);
            }
        }
    }
}

// ---------------------------------------------------------------------------
extern "C" void kernel_launch(void* const* d_in, const int* in_sizes, int n_in,
                              void* d_out, int out_size)
{
    // Positional defaults per metadata order: src, rot, ref_fft, gridF
    const float* src = (const float*)d_in[0];   // 8*2*192^3 = 113246208
    const float* rot = (n_in > 1) ? (const float*)d_in[1] : nullptr;  // 72
    const float* ref = (n_in > 2) ? (const float*)d_in[2] : nullptr;  // 262080
    for (int i = 0; i < n_in; i++) {
        switch (in_sizes[i]) {
            case 113246208: src = (const float*)d_in[i]; break;
            case 72:        rot = (const float*)d_in[i]; break;
            case 262080:    ref = (const float*)d_in[i]; break;
            default: break; // gridF unused — recomputed analytically
        }
    }
    float* out = (float*)d_out;

    kA_sample_ifft_y<<<NB * NX, 192>>>(src, rot, ref);
    kB_c2r_top4_final<<<NB * NRB, 192>>>(out);
}